// round 4
// baseline (speedup 1.0000x reference)
#include <cuda_runtime.h>
#include <cstdint>
#include <math.h>

#define B_SLIDES 64
#define N_CELLS  20000
#define NI       64
#define H1       16
#define H2       8
#define N_OUT    2

#define TPB      128
#define CSTAGE   256                 // cells staged per iteration (2 per thread)
#define ROW      68                  // padded floats per SMEM row (16B-aligned, conflict-free)
#define CHUNKS   6
#define CELLS_PER_CHUNK ((N_CELLS + CHUNKS - 1) / CHUNKS)   // 3334
#define TOTAL_BLOCKS (CHUNKS * B_SLIDES)                    // 384

#define XS_FLOATS (CSTAGE * ROW)     // 17408 floats = 69632 B
#define SMEM_BYTES (XS_FLOATS * 4 + 512 * 8 + 64 * 8 + 4 * 8 + 16 * 4 + 8 * 4 + 160)

typedef unsigned long long ull;

__device__ float        g_partials[B_SLIDES * CHUNKS * 9];
__device__ unsigned int g_count = 0;

__device__ __forceinline__ ull pack2(float lo, float hi) {
    ull r; asm("mov.b64 %0, {%1, %2};" : "=l"(r) : "f"(lo), "f"(hi)); return r;
}
__device__ __forceinline__ void unpack2(ull v, float& lo, float& hi) {
    asm("mov.b64 {%0, %1}, %2;" : "=f"(lo), "=f"(hi) : "l"(v));
}
// Packed fp32x2 FMA (sm_100+): two fp32 FMAs per instruction.
__device__ __forceinline__ ull fma2(ull a, ull b, ull c) {
    ull d; asm("fma.rn.f32x2 %0, %1, %2, %3;" : "=l"(d) : "l"(a), "l"(b), "l"(c)); return d;
}
__device__ __forceinline__ float ldcg(const float* p) {
    float v; asm("ld.global.cg.f32 %0, [%1];" : "=f"(v) : "l"(p)); return v;
}

// Per-cell tail: relu(h1) -> layer2 -> relu -> gate -> gated accumulate.
__device__ __forceinline__ void cell_tail(const ull* acc, bool valid,
                                          const ull* __restrict__ w2q,
                                          const float* __restrict__ b2s,
                                          const ull* __restrict__ wwp,
                                          float bwv,
                                          float& sw, ull* swh)
{
    float h1[H1];
    #pragma unroll
    for (int jp = 0; jp < 8; ++jp) {
        float lo, hi; unpack2(acc[jp], lo, hi);
        h1[2 * jp]     = fmaxf(lo, 0.f);
        h1[2 * jp + 1] = fmaxf(hi, 0.f);
    }

    ull acc2[4];
    #pragma unroll
    for (int kp = 0; kp < 4; ++kp) acc2[kp] = pack2(b2s[2 * kp], b2s[2 * kp + 1]);
    const ulonglong2* w2p = (const ulonglong2*)w2q;   // [16][2] of ull2
    #pragma unroll
    for (int i = 0; i < H1; ++i) {
        ull hx = pack2(h1[i], h1[i]);
        ulonglong2 wa = w2p[i * 2 + 0];
        ulonglong2 wb = w2p[i * 2 + 1];
        acc2[0] = fma2(hx, wa.x, acc2[0]);
        acc2[1] = fma2(hx, wa.y, acc2[1]);
        acc2[2] = fma2(hx, wb.x, acc2[2]);
        acc2[3] = fma2(hx, wb.y, acc2[3]);
    }

    float h2[H2];
    #pragma unroll
    for (int kp = 0; kp < 4; ++kp) {
        float lo, hi; unpack2(acc2[kp], lo, hi);
        h2[2 * kp]     = fmaxf(lo, 0.f);
        h2[2 * kp + 1] = fmaxf(hi, 0.f);
    }

    ull g = pack2(bwv, 0.f);
    #pragma unroll
    for (int kp = 0; kp < 4; ++kp)
        g = fma2(pack2(h2[2 * kp], h2[2 * kp + 1]), wwp[kp], g);
    float glo, ghi; unpack2(g, glo, ghi);
    float wgt = 1.f / (1.f + __expf(-(glo + ghi)));
    if (!valid) wgt = 0.f;

    sw += wgt;
    ull wp = pack2(wgt, wgt);
    #pragma unroll
    for (int kp = 0; kp < 4; ++kp)
        swh[kp] = fma2(wp, pack2(h2[2 * kp], h2[2 * kp + 1]), swh[kp]);
}

__global__ __launch_bounds__(TPB) void mlp_pool_kernel(
    const float* __restrict__ X,
    const float* __restrict__ W1, const float* __restrict__ b1,
    const float* __restrict__ W2, const float* __restrict__ b2,
    const float* __restrict__ Ww, const float* __restrict__ bw,
    const float* __restrict__ W4, const float* __restrict__ b4,
    float* __restrict__ out)
{
    extern __shared__ float smemf[];
    float* xs  = smemf;                                   // [CSTAGE][ROW]
    ull*   w1q = (ull*)(xs + XS_FLOATS);                  // 512 ull (W1 raw pairs)
    ull*   w2q = w1q + 512;                               // 64 ull
    ull*   wwp = w2q + 64;                                // 4 ull
    float* b1s = (float*)(wwp + 4);                       // 16
    float* b2s = b1s + 16;                                // 8
    float* red = b2s + 8;                                 // 9 * 4
    __shared__ unsigned int s_last;

    const int tid   = threadIdx.x;
    const int b     = blockIdx.y;
    const int chunk = blockIdx.x;

    // ---- weights -> SMEM (adjacent j-pairs are raw-contiguous) ----
    for (int k = tid; k < 512; k += TPB) w1q[k] = ((const ull*)W1)[k];
    if (tid < 64) w2q[tid] = ((const ull*)W2)[tid];
    if (tid < 4)  wwp[tid] = ((const ull*)Ww)[tid];
    if (tid < 16) b1s[tid] = b1[tid];
    if (tid < 8)  b2s[tid] = b2[tid];
    const float bwv = __ldg(bw);

    const int start = chunk * CELLS_PER_CHUNK;
    const int end   = min(start + CELLS_PER_CHUNK, N_CELLS);

    const float4* __restrict__ Xg = (const float4*)(X + (size_t)b * N_CELLS * NI);

    float sw = 0.f;
    ull swh[4];
    #pragma unroll
    for (int k = 0; k < 4; ++k) swh[k] = pack2(0.f, 0.f);

    for (int base = start; base < end; base += CSTAGE) {
        __syncthreads();                 // covers weight init + buffer reuse
        const int nv = min(end - base, CSTAGE);

        // ---- coalesced stage: 256 cells x 64 floats -> padded SMEM ----
        #pragma unroll
        for (int k = 0; k < 32; ++k) {
            int f = tid + k * TPB;        // 0..4095
            int c = f >> 4;               // cell 0..255
            int o = f & 15;               // float4 slot
            float4 v = make_float4(0.f, 0.f, 0.f, 0.f);
            if (c < nv) v = Xg[(size_t)(base + c) * (NI / 4) + o];
            *(float4*)&xs[c * ROW + o * 4] = v;
        }
        __syncthreads();

        // ---- layer 1 for 2 cells/thread; weights amortized over both ----
        ull accA[8], accB[8];
        #pragma unroll
        for (int jp = 0; jp < 8; ++jp) {
            ull bj = pack2(b1s[2 * jp], b1s[2 * jp + 1]);
            accA[jp] = bj; accB[jp] = bj;
        }

        const float4* xA = (const float4*)&xs[tid * ROW];
        const float4* xB = (const float4*)&xs[(tid + TPB) * ROW];

        #pragma unroll
        for (int i4 = 0; i4 < 16; ++i4) {
            float4 va = xA[i4];
            float4 vb = xB[i4];
            #pragma unroll
            for (int s = 0; s < 4; ++s) {
                float xa = (s == 0) ? va.x : (s == 1) ? va.y : (s == 2) ? va.z : va.w;
                float xb = (s == 0) ? vb.x : (s == 1) ? vb.y : (s == 2) ? vb.z : vb.w;
                ull xa2 = pack2(xa, xa);
                ull xb2 = pack2(xb, xb);
                const ulonglong2* wr = (const ulonglong2*)&w1q[(i4 * 4 + s) * 8];
                #pragma unroll
                for (int q = 0; q < 4; ++q) {
                    ulonglong2 w = wr[q];                 // LDS.128 broadcast
                    accA[2 * q + 0] = fma2(xa2, w.x, accA[2 * q + 0]);
                    accA[2 * q + 1] = fma2(xa2, w.y, accA[2 * q + 1]);
                    accB[2 * q + 0] = fma2(xb2, w.x, accB[2 * q + 0]);
                    accB[2 * q + 1] = fma2(xb2, w.y, accB[2 * q + 1]);
                }
            }
        }

        cell_tail(accA, tid < nv,       w2q, b2s, wwp, bwv, sw, swh);
        cell_tail(accB, tid + TPB < nv, w2q, b2s, wwp, bwv, sw, swh);
    }

    // ---- deterministic block reduction of 9 values ----
    float vals[9];
    vals[0] = sw;
    #pragma unroll
    for (int kp = 0; kp < 4; ++kp) {
        float lo, hi; unpack2(swh[kp], lo, hi);
        vals[1 + 2 * kp] = lo; vals[2 + 2 * kp] = hi;
    }
    #pragma unroll
    for (int off = 16; off > 0; off >>= 1) {
        #pragma unroll
        for (int k = 0; k < 9; ++k)
            vals[k] += __shfl_down_sync(0xffffffffu, vals[k], off);
    }
    const int lane = tid & 31, warp = tid >> 5;
    if (lane == 0) {
        #pragma unroll
        for (int k = 0; k < 9; ++k) red[k * 4 + warp] = vals[k];
    }
    __syncthreads();
    if (tid < 9) {
        float s = 0.f;
        #pragma unroll
        for (int w = 0; w < TPB / 32; ++w) s += red[tid * 4 + w];
        g_partials[((size_t)b * CHUNKS + chunk) * 9 + tid] = s;
    }

    // ---- last-block finalize (fused head; graph-replay-safe counter) ----
    __threadfence();
    __syncthreads();
    if (tid == 0) {
        unsigned int d = atomicAdd(&g_count, 1u);
        s_last = (d == TOTAL_BLOCKS - 1) ? 1u : 0u;
    }
    __syncthreads();

    if (s_last) {
        float* fs = xs;                  // reuse staging buffer: [64][9]
        for (int p = tid; p < B_SLIDES * 9; p += TPB) {
            int bb = p / 9, k = p % 9;
            float s = 0.f;
            #pragma unroll
            for (int c = 0; c < CHUNKS; ++c)
                s += ldcg(&g_partials[((size_t)bb * CHUNKS + c) * 9 + k]);
            fs[bb * 9 + k] = s;
        }
        __syncthreads();
        if (tid < B_SLIDES) {
            float inv = 1.f / fs[tid * 9];
            #pragma unroll
            for (int o = 0; o < N_OUT; ++o) {
                float r = b4[o];
                #pragma unroll
                for (int k = 0; k < H2; ++k)
                    r += (fs[tid * 9 + 1 + k] * inv) * W4[k * N_OUT + o];
                out[tid * N_OUT + o] = r;
            }
        }
        if (tid == 0) atomicExch(&g_count, 0u);   // reset for next graph replay
    }
}

extern "C" void kernel_launch(void* const* d_in, const int* in_sizes, int n_in,
                              void* d_out, int out_size)
{
    (void)in_sizes; (void)n_in; (void)out_size;
    cudaFuncSetAttribute(mlp_pool_kernel,
                         cudaFuncAttributeMaxDynamicSharedMemorySize, SMEM_BYTES);
    dim3 grid(CHUNKS, B_SLIDES);
    mlp_pool_kernel<<<grid, TPB, SMEM_BYTES>>>(
        (const float*)d_in[0],
        (const float*)d_in[1], (const float*)d_in[2],
        (const float*)d_in[3], (const float*)d_in[4],
        (const float*)d_in[5], (const float*)d_in[6],
        (const float*)d_in[7], (const float*)d_in[8],
        (float*)d_out);
}

// round 5
// speedup vs baseline: 1.1032x; 1.1032x over previous
#include <cuda_runtime.h>
#include <cstdint>
#include <math.h>

#define B_SLIDES 64
#define N_CELLS  20000
#define NI       64
#define H1       16
#define H2       8
#define N_OUT    2

#define TPB      128
#define CSTAGE   256                 // cells staged per iteration (2 per thread)
#define ROW      68                  // padded floats per SMEM row (16B-aligned, conflict-free)
#define CHUNKS   6
#define CELLS_PER_CHUNK ((N_CELLS + CHUNKS - 1) / CHUNKS)   // 3334
#define TOTAL_BLOCKS (CHUNKS * B_SLIDES)                    // 384

#define XS_FLOATS (CSTAGE * ROW)     // 17408 floats = 69632 B
#define SMEM_BYTES (XS_FLOATS * 4 + 512 * 8 + 64 * 8 + 4 * 8 + 16 * 4 + 8 * 4 + 160)

typedef unsigned long long ull;

__device__ float        g_partials[B_SLIDES * CHUNKS * 9];
__device__ unsigned int g_count = 0;

__device__ __forceinline__ ull pack2(float lo, float hi) {
    ull r; asm("mov.b64 %0, {%1, %2};" : "=l"(r) : "f"(lo), "f"(hi)); return r;
}
__device__ __forceinline__ void unpack2(ull v, float& lo, float& hi) {
    asm("mov.b64 {%0, %1}, %2;" : "=f"(lo), "=f"(hi) : "l"(v));
}
// Packed fp32x2 FMA (sm_100+): two fp32 FMAs per instruction.
__device__ __forceinline__ ull fma2(ull a, ull b, ull c) {
    ull d; asm("fma.rn.f32x2 %0, %1, %2, %3;" : "=l"(d) : "l"(a), "l"(b), "l"(c)); return d;
}
__device__ __forceinline__ float ldcg(const float* p) {
    float v; asm("ld.global.cg.f32 %0, [%1];" : "=f"(v) : "l"(p)); return v;
}

// Per-cell tail: relu(h1) -> layer2 -> relu -> gate -> gated accumulate.
__device__ __forceinline__ void cell_tail(const ull* acc, bool valid,
                                          const ull* __restrict__ w2q,
                                          const float* __restrict__ b2s,
                                          const ull* __restrict__ wwp,
                                          float bwv,
                                          float& sw, ull* swh)
{
    float h1[H1];
    #pragma unroll
    for (int jp = 0; jp < 8; ++jp) {
        float lo, hi; unpack2(acc[jp], lo, hi);
        h1[2 * jp]     = fmaxf(lo, 0.f);
        h1[2 * jp + 1] = fmaxf(hi, 0.f);
    }

    ull acc2[4];
    #pragma unroll
    for (int kp = 0; kp < 4; ++kp) acc2[kp] = pack2(b2s[2 * kp], b2s[2 * kp + 1]);
    const ulonglong2* w2p = (const ulonglong2*)w2q;   // [16][2] of ull2
    #pragma unroll
    for (int i = 0; i < H1; ++i) {
        ull hx = pack2(h1[i], h1[i]);
        ulonglong2 wa = w2p[i * 2 + 0];
        ulonglong2 wb = w2p[i * 2 + 1];
        acc2[0] = fma2(hx, wa.x, acc2[0]);
        acc2[1] = fma2(hx, wa.y, acc2[1]);
        acc2[2] = fma2(hx, wb.x, acc2[2]);
        acc2[3] = fma2(hx, wb.y, acc2[3]);
    }

    float h2[H2];
    #pragma unroll
    for (int kp = 0; kp < 4; ++kp) {
        float lo, hi; unpack2(acc2[kp], lo, hi);
        h2[2 * kp]     = fmaxf(lo, 0.f);
        h2[2 * kp + 1] = fmaxf(hi, 0.f);
    }

    ull g = pack2(bwv, 0.f);
    #pragma unroll
    for (int kp = 0; kp < 4; ++kp)
        g = fma2(pack2(h2[2 * kp], h2[2 * kp + 1]), wwp[kp], g);
    float glo, ghi; unpack2(g, glo, ghi);
    float wgt = 1.f / (1.f + __expf(-(glo + ghi)));
    if (!valid) wgt = 0.f;

    sw += wgt;
    ull wp = pack2(wgt, wgt);
    #pragma unroll
    for (int kp = 0; kp < 4; ++kp)
        swh[kp] = fma2(wp, pack2(h2[2 * kp], h2[2 * kp + 1]), swh[kp]);
}

__global__ __launch_bounds__(TPB, 3) void mlp_pool_kernel(
    const float* __restrict__ X,
    const float* __restrict__ W1, const float* __restrict__ b1,
    const float* __restrict__ W2, const float* __restrict__ b2,
    const float* __restrict__ Ww, const float* __restrict__ bw,
    const float* __restrict__ W4, const float* __restrict__ b4,
    float* __restrict__ out)
{
    extern __shared__ float smemf[];
    float* xs  = smemf;                                   // [CSTAGE][ROW]
    ull*   w1q = (ull*)(xs + XS_FLOATS);                  // 512 ull (W1 raw pairs)
    ull*   w2q = w1q + 512;                               // 64 ull
    ull*   wwp = w2q + 64;                                // 4 ull
    float* b1s = (float*)(wwp + 4);                       // 16
    float* b2s = b1s + 16;                                // 8
    float* red = b2s + 8;                                 // 9 * 4
    __shared__ unsigned int s_last;

    const int tid   = threadIdx.x;
    const int b     = blockIdx.y;
    const int chunk = blockIdx.x;

    // ---- weights -> SMEM (adjacent j-pairs are raw-contiguous) ----
    for (int k = tid; k < 512; k += TPB) w1q[k] = ((const ull*)W1)[k];
    if (tid < 64) w2q[tid] = ((const ull*)W2)[tid];
    if (tid < 4)  wwp[tid] = ((const ull*)Ww)[tid];
    if (tid < 16) b1s[tid] = b1[tid];
    if (tid < 8)  b2s[tid] = b2[tid];
    const float bwv = __ldg(bw);

    const int start = chunk * CELLS_PER_CHUNK;
    const int end   = min(start + CELLS_PER_CHUNK, N_CELLS);

    const float4* __restrict__ Xg = (const float4*)(X + (size_t)b * N_CELLS * NI);

    float sw = 0.f;
    ull swh[4];
    #pragma unroll
    for (int k = 0; k < 4; ++k) swh[k] = pack2(0.f, 0.f);

    for (int base = start; base < end; base += CSTAGE) {
        __syncthreads();                 // covers weight init + buffer reuse
        const int nv = min(end - base, CSTAGE);

        // ---- coalesced stage: 256 cells x 64 floats -> padded SMEM ----
        // unroll 8: keeps MLP=8 LDGs in flight without exploding registers
        #pragma unroll 8
        for (int k = 0; k < 32; ++k) {
            int f = tid + k * TPB;        // 0..4095
            int c = f >> 4;               // cell 0..255
            int o = f & 15;               // float4 slot
            float4 v = make_float4(0.f, 0.f, 0.f, 0.f);
            if (c < nv) v = Xg[(size_t)(base + c) * (NI / 4) + o];
            *(float4*)&xs[c * ROW + o * 4] = v;
        }
        __syncthreads();

        // ---- layer 1 for 2 cells/thread; weights amortized over both ----
        ull accA[8], accB[8];
        #pragma unroll
        for (int jp = 0; jp < 8; ++jp) {
            ull bj = pack2(b1s[2 * jp], b1s[2 * jp + 1]);
            accA[jp] = bj; accB[jp] = bj;
        }

        const float4* xA = (const float4*)&xs[tid * ROW];
        const float4* xB = (const float4*)&xs[(tid + TPB) * ROW];

        #pragma unroll 4
        for (int i4 = 0; i4 < 16; ++i4) {
            float4 va = xA[i4];
            float4 vb = xB[i4];
            #pragma unroll
            for (int s = 0; s < 4; ++s) {
                float xa = (s == 0) ? va.x : (s == 1) ? va.y : (s == 2) ? va.z : va.w;
                float xb = (s == 0) ? vb.x : (s == 1) ? vb.y : (s == 2) ? vb.z : vb.w;
                ull xa2 = pack2(xa, xa);
                ull xb2 = pack2(xb, xb);
                const ulonglong2* wr = (const ulonglong2*)&w1q[(i4 * 4 + s) * 8];
                #pragma unroll
                for (int q = 0; q < 4; ++q) {
                    ulonglong2 w = wr[q];                 // LDS.128 broadcast
                    accA[2 * q + 0] = fma2(xa2, w.x, accA[2 * q + 0]);
                    accA[2 * q + 1] = fma2(xa2, w.y, accA[2 * q + 1]);
                    accB[2 * q + 0] = fma2(xb2, w.x, accB[2 * q + 0]);
                    accB[2 * q + 1] = fma2(xb2, w.y, accB[2 * q + 1]);
                }
            }
        }

        cell_tail(accA, tid < nv,       w2q, b2s, wwp, bwv, sw, swh);
        cell_tail(accB, tid + TPB < nv, w2q, b2s, wwp, bwv, sw, swh);
    }

    // ---- deterministic block reduction of 9 values ----
    float vals[9];
    vals[0] = sw;
    #pragma unroll
    for (int kp = 0; kp < 4; ++kp) {
        float lo, hi; unpack2(swh[kp], lo, hi);
        vals[1 + 2 * kp] = lo; vals[2 + 2 * kp] = hi;
    }
    #pragma unroll
    for (int off = 16; off > 0; off >>= 1) {
        #pragma unroll
        for (int k = 0; k < 9; ++k)
            vals[k] += __shfl_down_sync(0xffffffffu, vals[k], off);
    }
    const int lane = tid & 31, warp = tid >> 5;
    if (lane == 0) {
        #pragma unroll
        for (int k = 0; k < 9; ++k) red[k * 4 + warp] = vals[k];
    }
    __syncthreads();
    if (tid < 9) {
        float s = 0.f;
        #pragma unroll
        for (int w = 0; w < TPB / 32; ++w) s += red[tid * 4 + w];
        g_partials[((size_t)b * CHUNKS + chunk) * 9 + tid] = s;
    }

    // ---- last-block finalize (fused head; graph-replay-safe counter) ----
    __threadfence();
    __syncthreads();
    if (tid == 0) {
        unsigned int d = atomicAdd(&g_count, 1u);
        s_last = (d == TOTAL_BLOCKS - 1) ? 1u : 0u;
    }
    __syncthreads();

    if (s_last) {
        float* fs = xs;                  // reuse staging buffer: [64][9]
        for (int p = tid; p < B_SLIDES * 9; p += TPB) {
            int bb = p / 9, k = p % 9;
            float s = 0.f;
            #pragma unroll
            for (int c = 0; c < CHUNKS; ++c)
                s += ldcg(&g_partials[((size_t)bb * CHUNKS + c) * 9 + k]);
            fs[bb * 9 + k] = s;
        }
        __syncthreads();
        if (tid < B_SLIDES) {
            float inv = 1.f / fs[tid * 9];
            #pragma unroll
            for (int o = 0; o < N_OUT; ++o) {
                float r = b4[o];
                #pragma unroll
                for (int k = 0; k < H2; ++k)
                    r += (fs[tid * 9 + 1 + k] * inv) * W4[k * N_OUT + o];
                out[tid * N_OUT + o] = r;
            }
        }
        if (tid == 0) atomicExch(&g_count, 0u);   // reset for next graph replay
    }
}

extern "C" void kernel_launch(void* const* d_in, const int* in_sizes, int n_in,
                              void* d_out, int out_size)
{
    (void)in_sizes; (void)n_in; (void)out_size;
    cudaFuncSetAttribute(mlp_pool_kernel,
                         cudaFuncAttributeMaxDynamicSharedMemorySize, SMEM_BYTES);
    dim3 grid(CHUNKS, B_SLIDES);
    mlp_pool_kernel<<<grid, TPB, SMEM_BYTES>>>(
        (const float*)d_in[0],
        (const float*)d_in[1], (const float*)d_in[2],
        (const float*)d_in[3], (const float*)d_in[4],
        (const float*)d_in[5], (const float*)d_in[6],
        (const float*)d_in[7], (const float*)d_in[8],
        (float*)d_out);
}